// round 2
// baseline (speedup 1.0000x reference)
#include <cuda_runtime.h>

// ============================================================================
// MH2SD: the reference's attention branch is algebraically dead.
//   v_spe1 = softmax over a size-1 axis  -> exactly 1.0
//   out    = attn @ ones = softmax row-sums -> exactly 1.0
// So: result[b,n,h] = 1 + gelu( bn( grouped 3x3 conv(x4, local_w) ) ),
// with x viewed flat as (b,128,24,24) and output written flat as
// b*73728 + och*576 + p  (the reshape is a pure memory reinterpret).
//
// conv: 2 groups, 64 in-ch -> 64 out-ch per group, 3x3, pad 1.
// bn:   y * gamma/sqrt(1+eps) + beta   (eps = 1e-5)
// gelu: exact, 0.5*z*(1+erf(z/sqrt(2)))
// ============================================================================

#define NPD   24
#define NPIX  576    // 24*24
#define DIMC  128

__global__ void __launch_bounds__(96)
conv_bn_gelu_kernel(const float* __restrict__ x,
                    const float* __restrict__ lw,
                    const float* __restrict__ gamma,
                    const float* __restrict__ beta,
                    float* __restrict__ out)
{
    // CTA decomposition: 2 batch x 2 group x 8 och-tiles(8 och) x 12 row-tiles(2 rows)
    const int cta = blockIdx.x;
    const int rt  = cta % 12;
    const int ot  = (cta / 12) & 7;
    const int g   = (cta / 96) & 1;
    const int b   = cta / 192;

    // smem: input planes for this group, rows r0-1 .. r0+2 (4 rows), cols -1..24 (26)
    //       weights transposed to [k = ci*9+di*3+dj][8 och] for float2 och-pair loads
    __shared__ __align__(16) float insm[64 * 4 * 26];   // 6656 floats
    __shared__ __align__(16) float wsm[576 * 8];        // 4608 floats

    const int tid = threadIdx.x;
    const int r0  = rt * 2;

    // ---- stage input (zero-padded halo) ----
    const float* xb = x + b * (DIMC * NPIX) + (g * 64) * NPIX;
    #pragma unroll 4
    for (int e = tid; e < 64 * 104; e += 96) {
        int ci  = e / 104;
        int rem = e - ci * 104;
        int rr  = rem / 26;
        int cc  = rem - rr * 26;
        int gr  = r0 - 1 + rr;
        int gc  = cc - 1;
        float v = 0.0f;
        if ((unsigned)gr < 24u && (unsigned)gc < 24u)
            v = xb[ci * NPIX + gr * NPD + gc];
        insm[e] = v;
    }

    // ---- stage weights, transposed [k][och] ----
    const float* wb = lw + (g * 64 + ot * 8) * 576;
    #pragma unroll 4
    for (int e = tid; e < 4608; e += 96) {
        int oo = e / 576;
        int k  = e - oo * 576;
        wsm[k * 8 + oo] = wb[oo * 576 + k];
    }
    __syncthreads();

    // ---- main loop: thread tile = 2 och x 2 px ----
    const int op  = tid & 3;        // och pair 0..3
    const int pg  = tid >> 2;       // pixel group 0..23
    const int row = pg / 12;        // 0..1 (local output row)
    const int col = 2 * (pg % 12);  // 0..22 (output col, even)

    float a00 = 0.f, a01 = 0.f, a10 = 0.f, a11 = 0.f;

    #pragma unroll 4
    for (int ci = 0; ci < 64; ci++) {
        // padded plane: output row `row` needs padded rows row..row+2,
        // padded cols col..col+3 cover input cols col-1..col+2
        const float*  pl = insm + ci * 104 + row * 26 + col;
        const float2* wc = (const float2*)wsm + ci * 36 + op;  // (k*8 + 2*op)/2
        #pragma unroll
        for (int di = 0; di < 3; di++) {
            float2 va = *(const float2*)(pl + di * 26);      // in[col-1], in[col]
            float2 vb = *(const float2*)(pl + di * 26 + 2);  // in[col+1], in[col+2]
            float2 w0 = wc[(di * 3 + 0) * 4];  // weights for (di, dj=0), och pair
            float2 w1 = wc[(di * 3 + 1) * 4];
            float2 w2 = wc[(di * 3 + 2) * 4];
            // dj=0: px0 uses va.x, px1 uses va.y
            a00 += w0.x * va.x;  a01 += w0.x * va.y;
            a10 += w0.y * va.x;  a11 += w0.y * va.y;
            // dj=1: px0 uses va.y, px1 uses vb.x
            a00 += w1.x * va.y;  a01 += w1.x * vb.x;
            a10 += w1.y * va.y;  a11 += w1.y * vb.x;
            // dj=2: px0 uses vb.x, px1 uses vb.y
            a00 += w2.x * vb.x;  a01 += w2.x * vb.y;
            a10 += w2.y * vb.x;  a11 += w2.y * vb.y;
        }
    }

    // ---- epilogue: bn + exact gelu + 1, write float2 per och ----
    const int ochL = ot * 8 + 2 * op;
    const int och0 = g * 64 + ochL;
    const float inv = rsqrtf(1.0f + 1e-5f);
    const float s0 = gamma[och0] * inv,     bb0 = beta[och0];
    const float s1 = gamma[och0 + 1] * inv, bb1 = beta[och0 + 1];

    const int p = (r0 + row) * NPD + col;
    float* o0 = out + (b * DIMC + och0) * NPIX + p;
    float* o1 = o0 + NPIX;

    float z00 = a00 * s0 + bb0, z01 = a01 * s0 + bb0;
    float z10 = a10 * s1 + bb1, z11 = a11 * s1 + bb1;

    const float kInvSqrt2 = 0.70710678118654752440f;
    float2 r0v, r1v;
    r0v.x = 1.0f + 0.5f * z00 * (1.0f + erff(z00 * kInvSqrt2));
    r0v.y = 1.0f + 0.5f * z01 * (1.0f + erff(z01 * kInvSqrt2));
    r1v.x = 1.0f + 0.5f * z10 * (1.0f + erff(z10 * kInvSqrt2));
    r1v.y = 1.0f + 0.5f * z11 * (1.0f + erff(z11 * kInvSqrt2));

    *(float2*)o0 = r0v;
    *(float2*)o1 = r1v;
}

extern "C" void kernel_launch(void* const* d_in, const int* in_sizes, int n_in,
                              void* d_out, int out_size) {
    const float* x     = (const float*)d_in[0];   // (2, 576, 128)
    const float* lw    = (const float*)d_in[9];   // local_w (128, 64, 3, 3)
    const float* bnc1g = (const float*)d_in[10];  // bnc1_gamma (128)
    const float* bnc1b = (const float*)d_in[11];  // bnc1_beta (128)
    float* out = (float*)d_out;                   // (2, 576, 128)

    conv_bn_gelu_kernel<<<384, 96>>>(x, lw, bnc1g, bnc1b, out);
}

// round 4
// speedup vs baseline: 1.0649x; 1.0649x over previous
#include <cuda_runtime.h>

// ============================================================================
// MH2SD: attention branch is algebraically dead (softmax over size-1 axis = 1,
// attn row-sums = 1), so out = 1 + gelu(bn(grouped 3x3 conv(x4, local_w))).
//
// R2: split-K over ci inside the CTA (2304 warps), packed fma.rn.f32x2,
// conflict-free padded smem layouts, duplicated weight pairs, fixed-role
// staging. Dynamic smem 69.6KB.
// ============================================================================

#define NPD   24
#define NPIX  576
#define DIMC  128

#define IN_CI_STRIDE 112            // 4 rows * 28 floats (halo-padded, 16B-aligned rows)
#define W_OFF        7168           // floats: 64 * 112
#define W_CI_STRIDE  160            // 8 och * 20 floats (9 dup-pairs + pad)
#define SMEM_FLOATS  (W_OFF + 64 * W_CI_STRIDE)   // 17408 floats = 69632 B

typedef unsigned long long u64;

__device__ __forceinline__ u64 pk(float lo, float hi) {
    u64 r; asm("mov.b64 %0, {%1, %2};" : "=l"(r) : "f"(lo), "f"(hi)); return r;
}
__device__ __forceinline__ void upk(float& lo, float& hi, u64 v) {
    asm("mov.b64 {%0, %1}, %2;" : "=f"(lo), "=f"(hi) : "l"(v));
}
__device__ __forceinline__ void ffma2(u64& d, u64 a, u64 b) {
    asm("fma.rn.f32x2 %0, %1, %2, %0;" : "+l"(d) : "l"(a), "l"(b));
}

__global__ void __launch_bounds__(192, 3)
conv_bn_gelu_f32x2(const float* __restrict__ x,
                   const float* __restrict__ lw,
                   const float* __restrict__ gamma,
                   const float* __restrict__ beta,
                   float* __restrict__ out)
{
    extern __shared__ float smem[];

    // CTA: 2 batch x 2 group x 8 och-tiles(8 och) x 12 row-tiles(2 rows)
    const int cta = blockIdx.x;
    const int rt  = cta % 12;
    const int ot  = (cta / 12) & 7;
    const int g   = (cta / 96) & 1;
    const int b   = cta / 192;
    const int tid = threadIdx.x;
    const int r0  = rt * 2;

    // ---- stage input: 256 row-tasks (ci, rr), halo at idx 0 and 25 ----
    const float* xb = x + b * (DIMC * NPIX) + g * 64 * NPIX;
    #pragma unroll
    for (int it = 0; it < 2; it++) {
        int task = tid + it * 192;
        if (task < 256) {
            int ci = task >> 2, rr = task & 3;
            int gr = r0 - 1 + rr;
            float* dst = smem + ci * IN_CI_STRIDE + rr * 28;
            if ((unsigned)gr < 24u) {
                const float4* src = (const float4*)(xb + ci * NPIX + gr * NPD);
                float4 v[6];
                #pragma unroll
                for (int q = 0; q < 6; q++) v[q] = src[q];
                dst[0]  = 0.0f;
                dst[25] = 0.0f;
                #pragma unroll
                for (int q = 0; q < 6; q++) {
                    dst[1 + 4*q] = v[q].x;  dst[2 + 4*q] = v[q].y;
                    dst[3 + 4*q] = v[q].z;  dst[4 + 4*q] = v[q].w;
                }
            } else {
                #pragma unroll
                for (int j = 0; j < 26; j++) dst[j] = 0.0f;
            }
        }
    }

    // ---- stage weights duplicated as (w,w) pairs: [ci][och][20 floats] ----
    const float* wb = lw + (g * 64 + ot * 8) * 576;
    #pragma unroll
    for (int it = 0; it < 3; it++) {
        int r = tid + it * 192;
        if (r < 512) {
            int och = r & 7, ci = r >> 3;
            const float* src = wb + och * 576 + ci * 9;
            float2* dst = (float2*)(smem + W_OFF + ci * W_CI_STRIDE + och * 20);
            #pragma unroll
            for (int t = 0; t < 9; t++) {
                float w = src[t];
                dst[t] = make_float2(w, w);
            }
        }
    }

    // ---- thread mapping: och(8) x [row(2) x colquad(6)] x cihalf(2) ----
    const int och  = tid & 7;
    const int rest = tid >> 3;          // 0..23
    const int half = rest / 12;         // tid<96 -> 0, tid>=96 -> 1
    const int s    = rest - half * 12;  // 0..11
    const int row  = s & 1;
    const int col  = (s >> 1) * 4;      // 0,4,8,12,16,20

    const int   ochg = g * 64 + ot * 8 + och;
    const float sc   = gamma[ochg] * rsqrtf(1.0f + 1e-5f);
    const float bb   = beta[ochg];

    __syncthreads();

    const float* ip = smem + half * 32 * IN_CI_STRIDE + row * 28 + col;
    const float* wp = smem + W_OFF + half * 32 * W_CI_STRIDE + och * 20;

    u64 acc01 = 0ull;   // packed (px0, px1)
    u64 acc23 = 0ull;   // packed (px2, px3)

    #pragma unroll 4
    for (int ci = 0; ci < 32; ci++) {
        const float* pl = ip + ci * IN_CI_STRIDE;
        const u64*   wq = (const u64*)(wp + ci * W_CI_STRIDE);
        #pragma unroll
        for (int di = 0; di < 3; di++) {
            float4 va = *(const float4*)(pl + di * 28);      // in[col-1..col+2]
            float2 vb = *(const float2*)(pl + di * 28 + 4);  // in[col+3..col+4]
            u64 P0 = pk(va.x, va.y);
            u64 P1 = pk(va.y, va.z);
            u64 P2 = pk(va.z, va.w);
            u64 P3 = pk(va.w, vb.x);
            u64 P4 = pk(vb.x, vb.y);
            u64 W0 = wq[di * 3 + 0];
            u64 W1 = wq[di * 3 + 1];
            u64 W2 = wq[di * 3 + 2];
            ffma2(acc01, P0, W0);
            ffma2(acc23, P2, W0);
            ffma2(acc01, P1, W1);
            ffma2(acc23, P3, W1);
            ffma2(acc01, P2, W2);
            ffma2(acc23, P4, W2);
        }
    }

    // ---- combine ci halves via smem (reuse weight region), epilogue ----
    __syncthreads();
    u64* red = (u64*)(smem + W_OFF);
    if (half == 1) {
        red[(tid - 96) * 2 + 0] = acc01;
        red[(tid - 96) * 2 + 1] = acc23;
    }
    __syncthreads();
    if (half == 0) {
        u64 q01 = red[tid * 2 + 0];
        u64 q23 = red[tid * 2 + 1];
        float p0, p1, p2, p3, q0, q1, q2, q3;
        upk(p0, p1, acc01);  upk(p2, p3, acc23);
        upk(q0, q1, q01);    upk(q2, q3, q23);

        float z0 = (p0 + q0) * sc + bb;
        float z1 = (p1 + q1) * sc + bb;
        float z2 = (p2 + q2) * sc + bb;
        float z3 = (p3 + q3) * sc + bb;

        const float kI = 0.70710678118654752440f;
        float4 o;
        o.x = 1.0f + 0.5f * z0 * (1.0f + erff(z0 * kI));
        o.y = 1.0f + 0.5f * z1 * (1.0f + erff(z1 * kI));
        o.z = 1.0f + 0.5f * z2 * (1.0f + erff(z2 * kI));
        o.w = 1.0f + 0.5f * z3 * (1.0f + erff(z3 * kI));

        *(float4*)(out + (b * DIMC + ochg) * NPIX + (r0 + row) * NPD + col) = o;
    }
}

extern "C" void kernel_launch(void* const* d_in, const int* in_sizes, int n_in,
                              void* d_out, int out_size) {
    const float* x     = (const float*)d_in[0];   // (2, 576, 128) flat
    const float* lw    = (const float*)d_in[9];   // local_w (128, 64, 3, 3)
    const float* bnc1g = (const float*)d_in[10];  // bnc1_gamma (128)
    const float* bnc1b = (const float*)d_in[11];  // bnc1_beta (128)
    float* out = (float*)d_out;

    cudaFuncSetAttribute(conv_bn_gelu_f32x2,
                         cudaFuncAttributeMaxDynamicSharedMemorySize,
                         SMEM_FLOATS * 4);
    conv_bn_gelu_f32x2<<<384, 192, SMEM_FLOATS * 4>>>(x, lw, bnc1g, bnc1b, out);
}